// round 4
// baseline (speedup 1.0000x reference)
#include <cuda_runtime.h>
#include <cstdint>
#include <limits.h>

#define NPTS 4096
#define DIM  768
#define WD   64
#define KTOP 100

#define BM 128
#define BK 16
#define NKT (DIM / BK)   // 48

// scratch (no allocations allowed)
__device__ int   g_counts[NPTS];
__device__ int   g_seed;
__device__ float g_simseed[NPTS];
__device__ int   g_s[NPTS];

// ---------------------------------------------------------------------------
// 0) init counts to 1 (diagonal sim[i][i] >= 0 always)
// ---------------------------------------------------------------------------
__global__ void init_counts() {
    int i = blockIdx.x * blockDim.x + threadIdx.x;
    if (i < NPTS) g_counts[i] = 1;
}

// ---------------------------------------------------------------------------
// 1) triangular count-GEMM: for i<j, c = (out_i . out_j >= 0); counts[i]+=c,
//    counts[j]+=c. 128x128 tile, 16x16 threads, 8x8 regs, double-buffered smem.
// ---------------------------------------------------------------------------
__global__ __launch_bounds__(256, 2)
void count_kernel(const float* __restrict__ X) {
    int bi = blockIdx.y, bj = blockIdx.x;
    if (bj < bi) return;

    __shared__ float As[2][BK][BM + 4];
    __shared__ float Bs[2][BK][BM + 4];
    __shared__ int rowSum[BM];
    __shared__ int colSum[BM];

    int tid = threadIdx.x;
    int tx = tid & 15, ty = tid >> 4;
    int i0 = bi * BM, j0 = bj * BM;

    int lrow = tid >> 1;          // 0..127
    int lq4  = (tid & 1) * 8;     // 8 consecutive floats per thread

    float acc[8][8];
    #pragma unroll
    for (int m = 0; m < 8; m++)
        #pragma unroll
        for (int n = 0; n < 8; n++) acc[m][n] = 0.0f;

    float4 ra0, ra1, rb0, rb1;

    const float* abase = X + (size_t)(i0 + lrow) * DIM + lq4;
    const float* bbase = X + (size_t)(j0 + lrow) * DIM + lq4;

#define LDG_TILE(kt) {                                         \
        const float* ap = abase + (kt) * BK;                   \
        const float* bp = bbase + (kt) * BK;                   \
        ra0 = *(const float4*)(ap);  ra1 = *(const float4*)(ap + 4); \
        rb0 = *(const float4*)(bp);  rb1 = *(const float4*)(bp + 4); }

#define STS_TILE(buf) {                                        \
        As[buf][lq4+0][lrow]=ra0.x; As[buf][lq4+1][lrow]=ra0.y; \
        As[buf][lq4+2][lrow]=ra0.z; As[buf][lq4+3][lrow]=ra0.w; \
        As[buf][lq4+4][lrow]=ra1.x; As[buf][lq4+5][lrow]=ra1.y; \
        As[buf][lq4+6][lrow]=ra1.z; As[buf][lq4+7][lrow]=ra1.w; \
        Bs[buf][lq4+0][lrow]=rb0.x; Bs[buf][lq4+1][lrow]=rb0.y; \
        Bs[buf][lq4+2][lrow]=rb0.z; Bs[buf][lq4+3][lrow]=rb0.w; \
        Bs[buf][lq4+4][lrow]=rb1.x; Bs[buf][lq4+5][lrow]=rb1.y; \
        Bs[buf][lq4+6][lrow]=rb1.z; Bs[buf][lq4+7][lrow]=rb1.w; }

    LDG_TILE(0);
    STS_TILE(0);
    __syncthreads();

    for (int kt = 0; kt < NKT; kt++) {
        int buf = kt & 1;
        if (kt + 1 < NKT) LDG_TILE(kt + 1);

        #pragma unroll
        for (int k = 0; k < BK; k++) {
            float a[8], b[8];
            #pragma unroll
            for (int m = 0; m < 8; m++) a[m] = As[buf][k][ty * 8 + m];
            #pragma unroll
            for (int n = 0; n < 8; n++) b[n] = Bs[buf][k][tx * 8 + n];
            #pragma unroll
            for (int m = 0; m < 8; m++)
                #pragma unroll
                for (int n = 0; n < 8; n++)
                    acc[m][n] += a[m] * b[n];
        }

        if (kt + 1 < NKT) STS_TILE(buf ^ 1);
        __syncthreads();
    }
#undef LDG_TILE
#undef STS_TILE

    // epilogue: count nonnegatives per row and per column
    if (tid < BM) { rowSum[tid] = 0; colSum[tid] = 0; }
    __syncthreads();

    bool diag = (bi == bj);
    int rcnt[8], ccnt[8];
    #pragma unroll
    for (int m = 0; m < 8; m++) rcnt[m] = 0;
    #pragma unroll
    for (int n = 0; n < 8; n++) ccnt[n] = 0;

    #pragma unroll
    for (int m = 0; m < 8; m++) {
        int gi = i0 + ty * 8 + m;
        #pragma unroll
        for (int n = 0; n < 8; n++) {
            int gj = j0 + tx * 8 + n;
            int c = (acc[m][n] >= 0.0f) && (!diag || gj > gi);
            rcnt[m] += c;
            ccnt[n] += c;
        }
    }
    #pragma unroll
    for (int m = 0; m < 8; m++) atomicAdd(&rowSum[ty * 8 + m], rcnt[m]);
    #pragma unroll
    for (int n = 0; n < 8; n++) atomicAdd(&colSum[tx * 8 + n], ccnt[n]);
    __syncthreads();

    if (tid < BM) {
        if (rowSum[tid]) atomicAdd(&g_counts[i0 + tid], rowSum[tid]);
        if (colSum[tid]) atomicAdd(&g_counts[j0 + tid], colSum[tid]);
    }
}

// ---------------------------------------------------------------------------
// 2) argmin of counts (first occurrence) + seed blend w/ round-half-to-even
// ---------------------------------------------------------------------------
__global__ void seed_kernel(const int* __restrict__ attn_seed) {
    __shared__ int bestC[256], bestI[256];
    int tid = threadIdx.x;
    int bc = INT_MAX, bi = 0;
    for (int i = tid; i < NPTS; i += 256) {
        int c = g_counts[i];
        if (c < bc) { bc = c; bi = i; }
    }
    bestC[tid] = bc; bestI[tid] = bi;
    __syncthreads();
    for (int s = 128; s > 0; s >>= 1) {
        if (tid < s) {
            if (bestC[tid + s] < bestC[tid] ||
                (bestC[tid + s] == bestC[tid] && bestI[tid + s] < bestI[tid])) {
                bestC[tid] = bestC[tid + s];
                bestI[tid] = bestI[tid + s];
            }
        }
        __syncthreads();
    }
    if (tid == 0) {
        int idx = bestI[0];
        int r = idx / WD, c = idx % WD;
        int tr = r + attn_seed[0];
        int tc = c + attn_seed[1];
        // round(0.5*(a+b)), half-to-even
        int rr = tr >> 1; if (tr & 1) rr += (rr & 1);
        int cc = tc >> 1; if (tc & 1) cc += (cc & 1);
        g_seed = rr * WD + cc;
    }
}

// ---------------------------------------------------------------------------
// 3) sim[seed][j] for all j + initial mask s[j] = (sim >= 0). warp per j.
// ---------------------------------------------------------------------------
__global__ void seedrow_kernel(const float* __restrict__ X) {
    int gwarp = (blockIdx.x * blockDim.x + threadIdx.x) >> 5;
    int lane  = threadIdx.x & 31;
    if (gwarp >= NPTS) return;
    int seed = g_seed;
    const float* xs = X + (size_t)seed * DIM;
    const float* xj = X + (size_t)gwarp * DIM;
    float p = 0.0f;
    for (int d = lane; d < DIM; d += 32) p += xs[d] * xj[d];
    #pragma unroll
    for (int o = 16; o > 0; o >>= 1) p += __shfl_down_sync(0xffffffffu, p, o);
    if (lane == 0) {
        g_simseed[gwarp] = p;
        g_s[gwarp] = (p >= 0.0f) ? 1 : 0;
    }
}

// ---------------------------------------------------------------------------
// 4) bitonic sort (desc value, asc index tiebreak) -> keep top-100, mask s
// ---------------------------------------------------------------------------
__global__ void topk_kernel() {
    __shared__ float sv[NPTS];
    __shared__ int   si[NPTS];
    int tid = threadIdx.x;   // 1024 threads
    int seed = g_seed;
    for (int i = tid; i < NPTS; i += 1024) { sv[i] = g_simseed[i]; si[i] = i; }
    __syncthreads();
    for (int k = 2; k <= NPTS; k <<= 1) {
        for (int j = k >> 1; j > 0; j >>= 1) {
            for (int i = tid; i < NPTS; i += 1024) {
                int ixj = i ^ j;
                if (ixj > i) {
                    float v1 = sv[i], v2 = sv[ixj];
                    int a = si[i], b = si[ixj];
                    // "greater" (comes later) = smaller value, or equal w/ larger idx
                    bool g = (v1 < v2) || (v1 == v2 && a > b);
                    bool dirAsc = ((i & k) == 0);
                    if (g == dirAsc) { sv[i] = v2; sv[ixj] = v1; si[i] = b; si[ixj] = a; }
                }
            }
            __syncthreads();
        }
    }
    float v99 = sv[KTOP - 1];
    int   i99 = si[KTOP - 1];
    for (int i = tid; i < NPTS; i += 1024) {
        int s = g_s[i];
        if (i == seed) s = 1;                      // reference sets s[seed]=1 pre-truncation
        float v = g_simseed[i];
        bool keep = (v > v99) || (v == v99 && i <= i99);
        g_s[i] = keep ? s : 0;
    }
}

// ---------------------------------------------------------------------------
// 5) sequential expansion: v = sum of kept features; for each kept i asc:
//    if out[i].v <= 0 -> drop i, v -= out[i]
// ---------------------------------------------------------------------------
__global__ void scan_kernel(const float* __restrict__ X) {
    __shared__ float v[DIM];
    __shared__ int   list[KTOP + 28];
    __shared__ int   na_s;
    __shared__ float red[256];
    int tid = threadIdx.x;   // 256 threads

    if (tid == 0) {
        int na = 0;
        for (int j = 0; j < NPTS; j++)
            if (g_s[j] && na < KTOP + 28) list[na++] = j;
        na_s = na;
    }
    __syncthreads();
    int na = na_s;

    for (int d = tid; d < DIM; d += 256) {
        float a = 0.0f;
        for (int l = 0; l < na; l++) a += X[(size_t)list[l] * DIM + d];
        v[d] = a;
    }
    __syncthreads();

    for (int l = 0; l < na; l++) {
        int i = list[l];
        const float* xi = X + (size_t)i * DIM;
        float p = 0.0f;
        for (int d = tid; d < DIM; d += 256) p += xi[d] * v[d];
        red[tid] = p;
        __syncthreads();
        for (int s = 128; s > 0; s >>= 1) {
            if (tid < s) red[tid] += red[tid + s];
            __syncthreads();
        }
        float dot = red[0];
        if (dot <= 0.0f) {                        // grows = (sum > 0) fails -> drop
            if (tid == 0) g_s[i] = 0;
            for (int d = tid; d < DIM; d += 256) v[d] -= xi[d];
        }
        __syncthreads();
    }
}

// ---------------------------------------------------------------------------
// 6) 8-connected components: in-place min-label propagation to fixpoint.
//    Output written as FLOAT (harness compares in the reference's float32
//    canonical dtype; int bit patterns read as denormals gave rel_err = 1.0).
// ---------------------------------------------------------------------------
__global__ void cc_kernel(float* __restrict__ outp) {
    __shared__ int lab[66 * 66];
    __shared__ int changed;
    const int BIG = NPTS + 1;
    int tid = threadIdx.x;   // 1024 threads

    for (int p = tid; p < 66 * 66; p += 1024) lab[p] = BIG;
    __syncthreads();

    int fgp[4], pos[4];
    #pragma unroll
    for (int q = 0; q < 4; q++) {
        int p = tid + q * 1024;
        int r = p >> 6, c = p & 63;
        pos[q] = (r + 1) * 66 + (c + 1);
        fgp[q] = g_s[p];
        lab[pos[q]] = fgp[q] ? (p + 1) : BIG;
    }
    __syncthreads();

    while (true) {
        if (tid == 0) changed = 0;
        __syncthreads();
        int lc = 0;
        #pragma unroll
        for (int q = 0; q < 4; q++) {
            if (fgp[q]) {
                int pp = pos[q];
                int m = lab[pp];
                m = min(m, lab[pp - 67]); m = min(m, lab[pp - 66]); m = min(m, lab[pp - 65]);
                m = min(m, lab[pp - 1]);                            m = min(m, lab[pp + 1]);
                m = min(m, lab[pp + 65]); m = min(m, lab[pp + 66]); m = min(m, lab[pp + 67]);
                if (m < lab[pp]) { lab[pp] = m; lc = 1; }
            }
        }
        if (lc) changed = 1;
        __syncthreads();
        int done = !changed;
        __syncthreads();          // protect 'changed' read vs next-iter reset
        if (done) break;
    }

    #pragma unroll
    for (int q = 0; q < 4; q++) {
        int p = tid + q * 1024;
        outp[p] = fgp[q] ? (float)lab[pos[q]] : 0.0f;
    }
}

// ---------------------------------------------------------------------------
extern "C" void kernel_launch(void* const* d_in, const int* in_sizes, int n_in,
                              void* d_out, int out_size) {
    // Robust input binding: the 2-element buffer is attn_seed, the big one is X.
    const float* X;
    const int*   attn;
    if (n_in >= 2 && in_sizes[0] == 2) {
        attn = (const int*)d_in[0];
        X    = (const float*)d_in[1];
    } else {
        X    = (const float*)d_in[0];
        attn = (const int*)d_in[1];
    }
    float* outp = (float*)d_out;                 // [64,64] labels, float32 canonical

    init_counts<<<16, 256>>>();
    count_kernel<<<dim3(32, 32), 256>>>(X);
    seed_kernel<<<1, 256>>>(attn);
    seedrow_kernel<<<NPTS / 8, 256>>>(X);
    topk_kernel<<<1, 1024>>>();
    scan_kernel<<<1, 256>>>(X);
    cc_kernel<<<1, 1024>>>(outp);
}